// round 13
// baseline (speedup 1.0000x reference)
#include <cuda_runtime.h>

#define Bb 512
#define Nn 10020
#define Ll 20
#define Ss 10
#define Hh 1001
#define HL 20020            // Hh * Ll
#define INV_SQRT6 0.40824829046386296f

// Output partition offsets (floats) in d_out, concat order:
// reconstructed, P, p1, p2, st, rot_axes, nw, contribution
#define O_REC 0
#define O_P   15390720
#define O_P1  16928256
#define O_P2  18465792
#define O_ST  20003328
#define O_ROT 50754048
#define O_NW  81504768
#define O_CB  91534788

// precompute tables, TRANSPOSED to [l][h] so hot-loop loads are coalesced
__device__ float4 g_t0[HL];   // [l*Hh + h] = (cos, sin, nw_g, scaling)
__device__ float4 g_t1[HL];   // [l*Hh + h] = (Wd0, Wd1, Wd2, 0)
__device__ float  g_rowsum[Nn];

// ---------------------------------------------------------------------------
// Kernel 0: per-(h,l) constant tables (transposed layout) + rowsum table
// ---------------------------------------------------------------------------
__global__ void k_tables(const float* __restrict__ angles,
                         const float* __restrict__ W_enc,
                         const float* __restrict__ W_dec,
                         const float* __restrict__ scaling)
{
    int idx = blockIdx.x * blockDim.x + threadIdx.x;
    if (idx < HL) {
        int l = idx / Hh, h = idx % Hh;     // h fastest -> coalesced writes
        int ai = h * Ll + l;                // angle / scaling index
        int n = Ss * h + l;                 // atom index
        int ha = n / Ss, l0 = n % Ss;
        float rs = 0.f;
        if (ha < Hh) rs += W_enc[(l0 * Hh + ha) * 3];
        if (ha >= 1) rs += W_enc[((l0 + Ss) * Hh + (ha - 1)) * 3];
        float a = angles[ai];
        float4 t0;
        t0.x = cosf(a);
        t0.y = sinf(a);
        t0.z = W_enc[(l * Hh + h) * 3] / rs;
        t0.w = scaling[n];
        g_t0[idx] = t0;
        float4 t1;
        t1.x = W_dec[(0 * Hh + h) * Ll + l];
        t1.y = W_dec[(1 * Hh + h) * Ll + l];
        t1.z = W_dec[(2 * Hh + h) * Ll + l];
        t1.w = 0.f;
        g_t1[idx] = t1;
    }
    if (idx < Nn) {
        int n = idx;
        int ha = n / Ss;
        float rs = 0.f;
        if (ha < Hh) rs += W_enc[((n % Ss) * Hh + ha) * 3];
        if (ha >= 1) rs += W_enc[((n % Ss + Ss) * Hh + ha - 1) * 3];
        g_rowsum[n] = rs;
    }
}

// ---------------------------------------------------------------------------
// SMEM XOR swizzle (preserves 16B granules within 128B rows)
// ---------------------------------------------------------------------------
__device__ __forceinline__ int swz(int a)   { return a ^ ((((a) >> 5) & 7) << 2); }
__device__ __forceinline__ int swz4(int v)  { return v ^ (((v) >> 3) & 7); }

// ---------------------------------------------------------------------------
// Fused kernel: 1D grid. Blocks [0, 4096): encode (b = idx>>3, hblk = idx&7).
// Blocks [4096, 6601): nw/contribution, 4 rows of n each.
// ---------------------------------------------------------------------------
#define HBLK 128
#define ENCB (8 * Bb)                     // 4096 encode blocks
#define NWB  ((Nn + 3) / 4)               // 2505 nw blocks
#define NPOS 1280
#define SXPOS (NPOS + Ll)                 // 1300 positions: [base-10, base+1290)
#define SXPAD 1304                        // padded plane stride
#define SXF   (SXPOS * 3)                 // 3900 floats of x window
#define BUFF  (HBLK * 60)                 // 7680 floats (rot staging / rec acc)
#define ACCF  (NPOS * 3)                  // 3840 floats

__device__ __forceinline__ void nw_vals(int h, int ended, int started,
                                        int ha, float wA, float wB,
                                        float& cb, float& nw)
{
    cb = (h >= ended && h < started) ? 1.f : 0.f;
    nw = (h == ha) ? wA : ((h == ha - 1) ? wB : 0.f);
}

__global__ __launch_bounds__(HBLK) void k_main(const float* __restrict__ x,
                                               const float* __restrict__ W_enc,
                                               float* __restrict__ out)
{
    __shared__ __align__(16) float sxp[3][SXPAD];
    __shared__ __align__(16) float buf[BUFF];
    __shared__ float sg[30];

    const int bidx = blockIdx.x;
    const int tid  = threadIdx.x;

    // ------------------------------- nw path -------------------------------
    if (bidx >= ENCB) {
        const int j = bidx - ENCB;
#pragma unroll
        for (int rrow = 0; rrow < 4; rrow++) {
            const int n = 4 * j + rrow;
            if (n >= Nn) break;
            const int started = (n < Nn - Ll) ? (n / Ss + 1) : Hh;
            const int ended   = (n >= Ll) ? ((n - Ss) / Ss) : 0;
            const int ha = n / Ss, l0 = n % Ss;
            const float inv_rs = 1.f / g_rowsum[n];
            const float wA = (ha < Hh) ? W_enc[(l0 * Hh + ha) * 3] * inv_rs : 0.f;
            const float wB = (ha >= 1) ? W_enc[((l0 + Ss) * Hh + ha - 1) * 3] * inv_rs : 0.f;

            const int bn = O_NW + n * Hh;
            const int bc = O_CB + n * Hh;
            const int head = (4 - (bn & 3)) & 3;

            for (int h = tid; h < head; h += HBLK) {
                float cb, nw; nw_vals(h, ended, started, ha, wA, wB, cb, nw);
                out[bn + h] = nw; out[bc + h] = cb;
            }
            const int nvec = (Hh - head) >> 2;
            float4* vn = (float4*)(out + bn + head);
            float4* vc = (float4*)(out + bc + head);
            for (int v = tid; v < nvec; v += HBLK) {
                int h = head + 4 * v;
                float4 c4, w4;
                nw_vals(h + 0, ended, started, ha, wA, wB, c4.x, w4.x);
                nw_vals(h + 1, ended, started, ha, wA, wB, c4.y, w4.y);
                nw_vals(h + 2, ended, started, ha, wA, wB, c4.z, w4.z);
                nw_vals(h + 3, ended, started, ha, wA, wB, c4.w, w4.w);
                vn[v] = w4; vc[v] = c4;
            }
            for (int h = head + 4 * nvec + tid; h < Hh; h += HBLK) {
                float cb, nw; nw_vals(h, ended, started, ha, wA, wB, cb, nw);
                out[bn + h] = nw; out[bc + h] = cb;
            }
        }
        return;
    }

    // ----------------------------- encode path -----------------------------
    const int b    = bidx >> 3;
    const int h0   = (bidx & 7) * HBLK;
    const int base = Ss * h0;

    // stage x window [base-10, base+1290) into 3 SoA planes
    const int xb = b * Nn * 3 + (base - Ss) * 3;
    for (int i = tid; i < SXF; i += HBLK) {
        int pos = i / 3, k = i - 3 * pos;
        int gp  = base - Ss + pos;
        sxp[k][pos] = (gp >= 0 && gp < Nn) ? x[xb + i] : 0.f;
    }
    __syncthreads();

    const int h = h0 + tid;
    const bool active = (h < Hh);
    float r[60];

    if (active) {
        float e00=0,e01=0,e02=0, e10=0,e11=0,e12=0, e20=0,e21=0,e22=0;
        const int wo = Ss * tid + Ss;
#pragma unroll
        for (int i = 0; i < Ll; i++) {
            const float* w = &W_enc[(i * Hh + h) * 3];
            float w0 = w[0], w1 = w[1], w2 = w[2];
            float x0 = sxp[0][wo + i];
            float x1 = sxp[1][wo + i];
            float x2 = sxp[2][wo + i];
            e00 += x0 * w0; e01 += x1 * w0; e02 += x2 * w0;
            e10 += x0 * w1; e11 += x1 * w1; e12 += x2 * w1;
            e20 += x0 * w2; e21 += x1 * w2; e22 += x2 * w2;
        }

        float Px = e00, Py = e01, Pz = e02;
        float d1x = e10 - Px, d1y = e11 - Py, d1z = e12 - Pz;
        float d2x = e20 - Px, d2y = e21 - Py, d2z = e22 - Pz;
        float n1 = sqrtf(d1x*d1x + d1y*d1y + d1z*d1z); if (n1 == 0.f) n1 = 1.f;
        float n2 = sqrtf(d2x*d2x + d2y*d2y + d2z*d2z); if (n2 == 0.f) n2 = 1.f;
        float i1 = 1.f / n1, i2 = 1.f / n2;
        float p1x = d1x*i1, p1y = d1y*i1, p1z = d1z*i1;
        float p2x = d2x*i2, p2y = d2y*i2, p2z = d2z*i2;
        float cx = (p1y*p2z - p1z*p2y) * INV_SQRT6;
        float cy = (p1z*p2x - p1x*p2z) * INV_SQRT6;
        float cz = (p1x*p2y - p1y*p2x) * INV_SQRT6;

        int pb = (b * Hh + h) * 3;
        out[O_P  + pb + 0] = Px;  out[O_P  + pb + 1] = Py;  out[O_P  + pb + 2] = Pz;
        out[O_P1 + pb + 0] = p1x; out[O_P1 + pb + 1] = p1y; out[O_P1 + pb + 2] = p1z;
        out[O_P2 + pb + 0] = p2x; out[O_P2 + pb + 1] = p2y; out[O_P2 + pb + 2] = p2z;

        // rot_axes -> swizzled SMEM staging; rec contributions -> registers
#pragma unroll
        for (int l = 0; l < Ll; l++) {
            float4 t1 = g_t1[l * Hh + h];
            float rxa = p1x * t1.x + p2x * t1.y + cx * t1.z;
            float rya = p1y * t1.x + p2y * t1.y + cy * t1.z;
            float rza = p1z * t1.x + p2z * t1.y + cz * t1.z;
            const int a0i = 60 * tid + 3 * l;
            buf[swz(a0i + 0)] = rxa;
            buf[swz(a0i + 1)] = rya;
            buf[swz(a0i + 2)] = rza;

            float4 t0 = g_t0[l * Hh + h];
            float qw = t0.x, s = t0.y, nwg = t0.z, sc = t0.w;
            float qx = s * rxa, qy = s * rya, qz = s * rza;
            float tw = -qx*p1x - qy*p1y - qz*p1z;
            float tx =  qw*p1x + qy*p1z - qz*p1y;
            float ty =  qw*p1y + qz*p1x - qx*p1z;
            float tz =  qw*p1z + qx*p1y - qy*p1x;
            float vx = -tw*qx + tx*qw - ty*qz + tz*qy;
            float vy = -tw*qy + ty*qw - tz*qx + tx*qz;
            float vz = -tw*qz + tz*qw - tx*qy + ty*qx;
            r[3*l + 0] = (sc * vx + Px) * nwg;
            r[3*l + 1] = (sc * vy + Py) * nwg;
            r[3*l + 2] = (sc * vz + Pz) * nwg;
        }
    }

    // ghost h0-1 (tid 0): rec contributions for l=10..19 into sg
    if (tid == 0 && h0 > 0) {
        const int hg = h0 - 1;
        float e00=0,e01=0,e02=0, e10=0,e11=0,e12=0, e20=0,e21=0,e22=0;
#pragma unroll
        for (int i = 0; i < Ll; i++) {
            const float* w = &W_enc[(i * Hh + hg) * 3];
            float w0 = w[0], w1 = w[1], w2 = w[2];
            float x0 = sxp[0][i];
            float x1 = sxp[1][i];
            float x2 = sxp[2][i];
            e00 += x0 * w0; e01 += x1 * w0; e02 += x2 * w0;
            e10 += x0 * w1; e11 += x1 * w1; e12 += x2 * w1;
            e20 += x0 * w2; e21 += x1 * w2; e22 += x2 * w2;
        }
        float Px = e00, Py = e01, Pz = e02;
        float d1x = e10 - Px, d1y = e11 - Py, d1z = e12 - Pz;
        float d2x = e20 - Px, d2y = e21 - Py, d2z = e22 - Pz;
        float n1 = sqrtf(d1x*d1x + d1y*d1y + d1z*d1z); if (n1 == 0.f) n1 = 1.f;
        float n2 = sqrtf(d2x*d2x + d2y*d2y + d2z*d2z); if (n2 == 0.f) n2 = 1.f;
        float i1 = 1.f / n1, i2 = 1.f / n2;
        float p1x = d1x*i1, p1y = d1y*i1, p1z = d1z*i1;
        float p2x = d2x*i2, p2y = d2y*i2, p2z = d2z*i2;
        float cx = (p1y*p2z - p1z*p2y) * INV_SQRT6;
        float cy = (p1z*p2x - p1x*p2z) * INV_SQRT6;
        float cz = (p1x*p2y - p1y*p2x) * INV_SQRT6;
#pragma unroll
        for (int l = Ss; l < Ll; l++) {
            float4 t1 = g_t1[l * Hh + hg];
            float rxa = p1x * t1.x + p2x * t1.y + cx * t1.z;
            float rya = p1y * t1.x + p2y * t1.y + cy * t1.z;
            float rza = p1z * t1.x + p2z * t1.y + cz * t1.z;
            float4 t0 = g_t0[l * Hh + hg];
            float qw = t0.x, s = t0.y, nwg = t0.z, sc = t0.w;
            float qx = s * rxa, qy = s * rya, qz = s * rza;
            float tw = -qx*p1x - qy*p1y - qz*p1z;
            float tx =  qw*p1x + qy*p1z - qz*p1y;
            float ty =  qw*p1y + qz*p1x - qx*p1z;
            float tz =  qw*p1z + qx*p1y - qy*p1x;
            float vx = -tw*qx + tx*qw - ty*qz + tz*qy;
            float vy = -tw*qy + ty*qw - tz*qx + tx*qz;
            float vz = -tw*qz + tz*qw - tx*qy + ty*qx;
            sg[3*(l-Ss) + 0] = (sc * vx + Px) * nwg;
            sg[3*(l-Ss) + 1] = (sc * vy + Py) * nwg;
            sg[3*(l-Ss) + 2] = (sc * vz + Pz) * nwg;
        }
    }
    __syncthreads();

    const int m = (Hh - h0 < HBLK) ? (Hh - h0) : HBLK;   // active h count

    // rot writeout: coalesced float4 dst, swizzled granule src
    {
        const int rb = O_ROT + (b * Hh + h0) * 60;       // mod 4 == 0
        const int nv = (60 * m) >> 2;
        const float4* src = (const float4*)buf;
        float4* dst = (float4*)(out + rb);
        for (int v = tid; v < nv; v += HBLK) dst[v] = src[swz4(v)];
    }

    // st writeout: float4 reshuffle from SoA planes
    for (int i = 0; i < Ll; i++) {
        const int rb = O_ST + (b * Ll + i) * (Hh * 3) + h0 * 3;
        const int rowf = 3 * m;
        const int head = (4 - (rb & 3)) & 3;
        for (int f = tid; f < head; f += HBLK) {
            int dh = f / 3, k = f - 3 * dh;
            out[rb + f] = sxp[k][Ss * dh + Ss + i];
        }
        const int nv = (rowf - head) >> 2;
        for (int v = tid; v < nv; v += HBLK) {
            int f0 = head + 4 * v;
            float4 q;
            int e0 = f0, e1 = f0+1, e2 = f0+2, e3 = f0+3;
            int d0 = e0/3, d1 = e1/3, d2 = e2/3, d3 = e3/3;
            q.x = sxp[e0 - 3*d0][Ss*d0 + Ss + i];
            q.y = sxp[e1 - 3*d1][Ss*d1 + Ss + i];
            q.z = sxp[e2 - 3*d2][Ss*d2 + Ss + i];
            q.w = sxp[e3 - 3*d3][Ss*d3 + Ss + i];
            *(float4*)(out + rb + f0) = q;
        }
        for (int f = head + 4*nv + tid; f < rowf; f += HBLK) {
            int dh = f / 3, k = f - 3 * dh;
            out[rb + f] = sxp[k][Ss * dh + Ss + i];
        }
    }
    __syncthreads();

    // rec accumulation into swizzled buf[0..3840):
    // phase 1: even tids STORE their 60 floats
    if (active && ((tid & 1) == 0)) {
#pragma unroll
        for (int j = 0; j < 60; j++) buf[swz(30 * tid + j)] = r[j];
    }
    __syncthreads();
    // phase 2: odd tids ADD (tid 127 only its first 30)
    if (active && ((tid & 1) == 1)) {
        const int jmax = (tid == HBLK - 1) ? 30 : 60;
        for (int j = 0; j < jmax; j++) buf[swz(30 * tid + j)] += r[j];
    }
    if (tid == 0 && h0 > 0) {
#pragma unroll
        for (int j = 0; j < 30; j++) buf[swz(j)] += sg[j];
    }
    __syncthreads();

    // rec writeback: coalesced float4 plain stores (exclusive ownership)
    {
        const int gb = (b * Nn + base) * 3;              // O_REC == 0, mod 4 == 0
        int maxf = (Nn - base) * 3;
        if (maxf > ACCF) maxf = ACCF;
        const int nv = maxf >> 2;                        // divisible by 4
        const float4* src = (const float4*)buf;
        float4* dst = (float4*)(out + gb);
        for (int v = tid; v < nv; v += HBLK) dst[v] = src[swz4(v)];
    }
}

// ---------------------------------------------------------------------------
extern "C" void kernel_launch(void* const* d_in, const int* in_sizes, int n_in,
                              void* d_out, int out_size)
{
    const float* x       = (const float*)d_in[0];
    const float* W_enc   = (const float*)d_in[1];
    const float* W_dec   = (const float*)d_in[2];
    const float* angles  = (const float*)d_in[3];
    const float* scaling = (const float*)d_in[4];
    float* out = (float*)d_out;

    k_tables<<<(HL + 255) / 256, 256>>>(angles, W_enc, W_dec, scaling);

    k_main<<<ENCB + NWB, HBLK>>>(x, W_enc, out);
}

// round 14
// speedup vs baseline: 1.2480x; 1.2480x over previous
#include <cuda_runtime.h>

#define Bb 512
#define Nn 10020
#define Ll 20
#define Ss 10
#define Hh 1001
#define HL 20020            // Hh * Ll
#define INV_SQRT6 0.40824829046386296f

// Output partition offsets (floats) in d_out, concat order:
// reconstructed, P, p1, p2, st, rot_axes, nw, contribution
#define O_REC 0
#define O_P   15390720
#define O_P1  16928256
#define O_P2  18465792
#define O_ST  20003328
#define O_ROT 50754048
#define O_NW  81504768
#define O_CB  91534788

// precompute tables, TRANSPOSED to [l][h] so hot-loop loads are coalesced
__device__ float4 g_t0[HL];   // [l*Hh + h] = (cos, sin, nw_g, scaling)
__device__ float4 g_t1[HL];   // [l*Hh + h] = (Wd0, Wd1, Wd2, 0)
__device__ float  g_rowsum[Nn];

// ---------------------------------------------------------------------------
// Kernel 0: per-(h,l) constant tables (transposed layout) + rowsum table
// ---------------------------------------------------------------------------
__global__ void k_tables(const float* __restrict__ angles,
                         const float* __restrict__ W_enc,
                         const float* __restrict__ W_dec,
                         const float* __restrict__ scaling)
{
    int idx = blockIdx.x * blockDim.x + threadIdx.x;
    if (idx < HL) {
        int l = idx / Hh, h = idx % Hh;     // h fastest -> coalesced writes
        int ai = h * Ll + l;                // angle / scaling index
        int n = Ss * h + l;                 // atom index
        int ha = n / Ss, l0 = n % Ss;
        float rs = 0.f;
        if (ha < Hh) rs += W_enc[(l0 * Hh + ha) * 3];
        if (ha >= 1) rs += W_enc[((l0 + Ss) * Hh + (ha - 1)) * 3];
        float a = angles[ai];
        float4 t0;
        t0.x = cosf(a);
        t0.y = sinf(a);
        t0.z = W_enc[(l * Hh + h) * 3] / rs;
        t0.w = scaling[n];
        g_t0[idx] = t0;
        float4 t1;
        t1.x = W_dec[(0 * Hh + h) * Ll + l];
        t1.y = W_dec[(1 * Hh + h) * Ll + l];
        t1.z = W_dec[(2 * Hh + h) * Ll + l];
        t1.w = 0.f;
        g_t1[idx] = t1;
    }
    if (idx < Nn) {
        int n = idx;
        int ha = n / Ss;
        float rs = 0.f;
        if (ha < Hh) rs += W_enc[((n % Ss) * Hh + ha) * 3];
        if (ha >= 1) rs += W_enc[((n % Ss + Ss) * Hh + ha - 1) * 3];
        g_rowsum[n] = rs;
    }
}

// ---------------------------------------------------------------------------
// SMEM XOR swizzle (bits 2-4 ^= bits 5-7; stays within 32-float chunk)
// ---------------------------------------------------------------------------
__device__ __forceinline__ int swz(int a)   { return a ^ ((((a) >> 5) & 7) << 2); }
__device__ __forceinline__ int swz4(int v)  { return v ^ (((v) >> 3) & 7); }

// ---------------------------------------------------------------------------
// Encode kernel. Block = 64 consecutive h, grid = (16, B). ~24KB SMEM,
// <=113 regs -> up to 9 blocks/SM. rec accumulation via shfl_up pairing:
// iteration j handles l=j (own) and l=j+10 (shuffled to tid+1).
// ---------------------------------------------------------------------------
#define HBLK 64
#define HBN  16                           // hblocks per batch
#define NPOS (Ss * HBLK)                  // 640 positions owned per block
#define SXPOS (NPOS + Ll)                 // 660 positions: [base-10, base+650)
#define SXF   (SXPOS * 3)                 // 1980 floats
#define BUFF  (HBLK * 60)                 // 3840 floats (rot staging / rec acc)
#define ACCF  (NPOS * 3)                  // 1920 floats

__global__ __launch_bounds__(HBLK, 9) void k_encode(const float* __restrict__ x,
                                                    const float* __restrict__ W_enc,
                                                    float* __restrict__ out)
{
    __shared__ __align__(16) float sx [SXF];
    __shared__ __align__(16) float buf[BUFF];
    __shared__ float sg[30];              // ghost (h0-1) l=10..19 contributions
    __shared__ float swb[2][30];          // warp-boundary l=10..19 contributions

    const int b    = blockIdx.y;
    const int h0   = blockIdx.x * HBLK;
    const int tid  = threadIdx.x;
    const int wid  = tid >> 5;
    const int lane = tid & 31;
    const int base = Ss * h0;

    // stage x window [base-10, base+650)
    const int xb = b * Nn * 3 + (base - Ss) * 3;
    for (int i = tid; i < SXF; i += HBLK) {
        int pos = base - Ss + i / 3;
        sx[i] = (pos >= 0 && pos < Nn) ? x[xb + i] : 0.f;
    }
    __syncthreads();

    const int h = h0 + tid;
    const bool active = (h < Hh);
    const int hc = active ? h : (Hh - 1);        // clamped for table loads

    // ---- frame ----
    float Px=0,Py=0,Pz=0, p1x=0,p1y=0,p1z=0, p2x=0,p2y=0,p2z=0, cx=0,cy=0,cz=0;
    {
        float e00=0,e01=0,e02=0, e10=0,e11=0,e12=0, e20=0,e21=0,e22=0;
        const int lo = 30 * tid + 30;
#pragma unroll
        for (int i = 0; i < Ll; i++) {
            const float* w = &W_enc[(i * Hh + hc) * 3];
            float w0 = w[0], w1 = w[1], w2 = w[2];
            float x0 = sx[lo + 3*i + 0];
            float x1 = sx[lo + 3*i + 1];
            float x2 = sx[lo + 3*i + 2];
            e00 += x0 * w0; e01 += x1 * w0; e02 += x2 * w0;
            e10 += x0 * w1; e11 += x1 * w1; e12 += x2 * w1;
            e20 += x0 * w2; e21 += x1 * w2; e22 += x2 * w2;
        }
        Px = e00; Py = e01; Pz = e02;
        float d1x = e10 - Px, d1y = e11 - Py, d1z = e12 - Pz;
        float d2x = e20 - Px, d2y = e21 - Py, d2z = e22 - Pz;
        float n1 = sqrtf(d1x*d1x + d1y*d1y + d1z*d1z); if (n1 == 0.f) n1 = 1.f;
        float n2 = sqrtf(d2x*d2x + d2y*d2y + d2z*d2z); if (n2 == 0.f) n2 = 1.f;
        float i1 = 1.f / n1, i2 = 1.f / n2;
        p1x = d1x*i1; p1y = d1y*i1; p1z = d1z*i1;
        p2x = d2x*i2; p2y = d2y*i2; p2z = d2z*i2;
        cx = (p1y*p2z - p1z*p2y) * INV_SQRT6;
        cy = (p1z*p2x - p1x*p2z) * INV_SQRT6;
        cz = (p1x*p2y - p1y*p2x) * INV_SQRT6;
    }

    if (active) {
        int pb = (b * Hh + h) * 3;
        out[O_P  + pb + 0] = Px;  out[O_P  + pb + 1] = Py;  out[O_P  + pb + 2] = Pz;
        out[O_P1 + pb + 0] = p1x; out[O_P1 + pb + 1] = p1y; out[O_P1 + pb + 2] = p1z;
        out[O_P2 + pb + 0] = p2x; out[O_P2 + pb + 1] = p2y; out[O_P2 + pb + 2] = p2z;
    }

    // ---- rot staging + rec accumulation (paired l / l+10, shfl pass) ----
    float a[30];
#pragma unroll
    for (int j = 0; j < Ss; j++) {
        float c0=0.f, c1=0.f, c2=0.f;      // own contribution (l = j)
        float d0=0.f, d1v=0.f, d2v=0.f;    // neighbor contribution (l = j+10)
        {
            float4 t1 = g_t1[j * Hh + hc];
            float rxa = p1x * t1.x + p2x * t1.y + cx * t1.z;
            float rya = p1y * t1.x + p2y * t1.y + cy * t1.z;
            float rza = p1z * t1.x + p2z * t1.y + cz * t1.z;
            const int ai = 60 * tid + 3 * j;
            buf[swz(ai + 0)] = rxa;
            buf[swz(ai + 1)] = rya;
            buf[swz(ai + 2)] = rza;
            if (active) {
                float4 t0 = g_t0[j * Hh + hc];
                float qw = t0.x, s = t0.y, nwg = t0.z, sc = t0.w;
                float qx = s * rxa, qy = s * rya, qz = s * rza;
                float tw = -qx*p1x - qy*p1y - qz*p1z;
                float tx =  qw*p1x + qy*p1z - qz*p1y;
                float ty =  qw*p1y + qz*p1x - qx*p1z;
                float tz =  qw*p1z + qx*p1y - qy*p1x;
                float vx = -tw*qx + tx*qw - ty*qz + tz*qy;
                float vy = -tw*qy + ty*qw - tz*qx + tx*qz;
                float vz = -tw*qz + tz*qw - tx*qy + ty*qx;
                c0 = (sc * vx + Px) * nwg;
                c1 = (sc * vy + Py) * nwg;
                c2 = (sc * vz + Pz) * nwg;
            }
        }
        {
            const int l = j + Ss;
            float4 t1 = g_t1[l * Hh + hc];
            float rxa = p1x * t1.x + p2x * t1.y + cx * t1.z;
            float rya = p1y * t1.x + p2y * t1.y + cy * t1.z;
            float rza = p1z * t1.x + p2z * t1.y + cz * t1.z;
            const int ai = 60 * tid + 3 * l;
            buf[swz(ai + 0)] = rxa;
            buf[swz(ai + 1)] = rya;
            buf[swz(ai + 2)] = rza;
            if (active) {
                float4 t0 = g_t0[l * Hh + hc];
                float qw = t0.x, s = t0.y, nwg = t0.z, sc = t0.w;
                float qx = s * rxa, qy = s * rya, qz = s * rza;
                float tw = -qx*p1x - qy*p1y - qz*p1z;
                float tx =  qw*p1x + qy*p1z - qz*p1y;
                float ty =  qw*p1y + qz*p1x - qx*p1z;
                float tz =  qw*p1z + qx*p1y - qy*p1x;
                float vx = -tw*qx + tx*qw - ty*qz + tz*qy;
                float vy = -tw*qy + ty*qw - tz*qx + tx*qz;
                float vz = -tw*qz + tz*qw - tx*qy + ty*qx;
                d0  = (sc * vx + Px) * nwg;
                d1v = (sc * vy + Py) * nwg;
                d2v = (sc * vz + Pz) * nwg;
            }
        }
        // pass l+10 contribution to tid+1
        float e0 = __shfl_up_sync(0xffffffffu, d0, 1);
        float e1 = __shfl_up_sync(0xffffffffu, d1v, 1);
        float e2 = __shfl_up_sync(0xffffffffu, d2v, 1);
        bool has = (lane != 0);
        a[3*j + 0] = c0 + (has ? e0 : 0.f);
        a[3*j + 1] = c1 + (has ? e1 : 0.f);
        a[3*j + 2] = c2 + (has ? e2 : 0.f);
        if (lane == 31 && wid == 0) {       // warp 0 -> warp 1 boundary
            swb[0][3*j + 0] = d0;
            swb[0][3*j + 1] = d1v;
            swb[0][3*j + 2] = d2v;
        }
    }

    // ghost h0-1 (tid 0): rec contributions for l=10..19 into sg
    if (tid == 0 && h0 > 0) {
        const int hg = h0 - 1;
        float e00=0,e01=0,e02=0, e10=0,e11=0,e12=0, e20=0,e21=0,e22=0;
#pragma unroll
        for (int i = 0; i < Ll; i++) {
            const float* w = &W_enc[(i * Hh + hg) * 3];
            float w0 = w[0], w1 = w[1], w2 = w[2];
            float x0 = sx[3*i + 0];
            float x1 = sx[3*i + 1];
            float x2 = sx[3*i + 2];
            e00 += x0 * w0; e01 += x1 * w0; e02 += x2 * w0;
            e10 += x0 * w1; e11 += x1 * w1; e12 += x2 * w1;
            e20 += x0 * w2; e21 += x1 * w2; e22 += x2 * w2;
        }
        float gPx = e00, gPy = e01, gPz = e02;
        float d1x = e10 - gPx, d1y = e11 - gPy, d1z = e12 - gPz;
        float d2x = e20 - gPx, d2y = e21 - gPy, d2z = e22 - gPz;
        float n1 = sqrtf(d1x*d1x + d1y*d1y + d1z*d1z); if (n1 == 0.f) n1 = 1.f;
        float n2 = sqrtf(d2x*d2x + d2y*d2y + d2z*d2z); if (n2 == 0.f) n2 = 1.f;
        float i1 = 1.f / n1, i2 = 1.f / n2;
        float q1x = d1x*i1, q1y = d1y*i1, q1z = d1z*i1;
        float q2x = d2x*i2, q2y = d2y*i2, q2z = d2z*i2;
        float gcx = (q1y*q2z - q1z*q2y) * INV_SQRT6;
        float gcy = (q1z*q2x - q1x*q2z) * INV_SQRT6;
        float gcz = (q1x*q2y - q1y*q2x) * INV_SQRT6;
#pragma unroll
        for (int l = Ss; l < Ll; l++) {
            float4 t1 = g_t1[l * Hh + hg];
            float rxa = q1x * t1.x + q2x * t1.y + gcx * t1.z;
            float rya = q1y * t1.x + q2y * t1.y + gcy * t1.z;
            float rza = q1z * t1.x + q2z * t1.y + gcz * t1.z;
            float4 t0 = g_t0[l * Hh + hg];
            float qw = t0.x, s = t0.y, nwg = t0.z, sc = t0.w;
            float qx = s * rxa, qy = s * rya, qz = s * rza;
            float tw = -qx*q1x - qy*q1y - qz*q1z;
            float tx =  qw*q1x + qy*q1z - qz*q1y;
            float ty =  qw*q1y + qz*q1x - qx*q1z;
            float tz =  qw*q1z + qx*q1y - qy*q1x;
            float vx = -tw*qx + tx*qw - ty*qz + tz*qy;
            float vy = -tw*qy + ty*qw - tz*qx + tx*qz;
            float vz = -tw*qz + tz*qw - tx*qy + ty*qx;
            sg[3*(l-Ss) + 0] = (sc * vx + gPx) * nwg;
            sg[3*(l-Ss) + 1] = (sc * vy + gPy) * nwg;
            sg[3*(l-Ss) + 2] = (sc * vz + gPz) * nwg;
        }
    }
    __syncthreads();

    const int m = (Hh - h0 < HBLK) ? (Hh - h0) : HBLK;   // active h count

    // rot writeout: coalesced float4 dst, swizzled granule src
    {
        const int rb = O_ROT + (b * Hh + h0) * 60;       // mod 4 == 0
        const int nv = (60 * m) >> 2;
        const float4* src = (const float4*)buf;
        float4* dst = (float4*)(out + rb);
        for (int v = tid; v < nv; v += HBLK) dst[v] = src[swz4(v)];
    }

    // st writeout: float4 reshuffle of sx. st[b,i,h,k] = x[b, 10h+i, k]
    for (int i = 0; i < Ll; i++) {
        const int rb = O_ST + (b * Ll + i) * (Hh * 3) + h0 * 3;
        const int rowf = 3 * m;
        const int head = (4 - (rb & 3)) & 3;
        for (int f = tid; f < head; f += HBLK) {
            int dh = f / 3, k = f - 3 * dh;
            out[rb + f] = sx[30 * dh + 30 + 3*i + k];
        }
        const int nv = (rowf - head) >> 2;
        for (int v = tid; v < nv; v += HBLK) {
            int f0 = head + 4 * v;
            float4 q;
            int d0=(f0+0)/3, d1=(f0+1)/3, d2=(f0+2)/3, d3=(f0+3)/3;
            q.x = sx[30*d0 + 30 + 3*i + (f0+0) - 3*d0];
            q.y = sx[30*d1 + 30 + 3*i + (f0+1) - 3*d1];
            q.z = sx[30*d2 + 30 + 3*i + (f0+2) - 3*d2];
            q.w = sx[30*d3 + 30 + 3*i + (f0+3) - 3*d3];
            *(float4*)(out + rb + f0) = q;
        }
        for (int f = head + 4*nv + tid; f < rowf; f += HBLK) {
            int dh = f / 3, k = f - 3 * dh;
            out[rb + f] = sx[30 * dh + 30 + 3*i + k];
        }
    }
    __syncthreads();    // all buf reads (rot) done before acc overwrite

    // boundary fixups, then write acc into buf (exclusive 30-float regions)
    if (lane == 0) {
        if (tid == 0) {
            if (h0 > 0) {
#pragma unroll
                for (int j = 0; j < 30; j++) a[j] += sg[j];
            }
        } else {
#pragma unroll
            for (int j = 0; j < 30; j++) a[j] += swb[wid - 1][j];
        }
    }
    if (base + Ss * tid < Nn) {
#pragma unroll
        for (int j = 0; j < 30; j++) buf[swz(30 * tid + j)] = a[j];
    }
    __syncthreads();

    // rec writeback: coalesced float4 plain stores (exclusive ownership)
    {
        const int gb = (b * Nn + base) * 3;              // O_REC == 0, mod 4 == 0
        int maxf = (Nn - base) * 3;
        if (maxf > ACCF) maxf = ACCF;
        const int nv = maxf >> 2;                        // divisible by 4
        const float4* src = (const float4*)buf;
        float4* dst = (float4*)(out + gb);
        for (int v = tid; v < nv; v += HBLK) dst[v] = src[swz4(v)];
    }
}

// ---------------------------------------------------------------------------
// k_nw: one block per n, vectorized float4 row writes for nw + contribution
// ---------------------------------------------------------------------------
__device__ __forceinline__ void nw_vals(int h, int ended, int started,
                                        int ha, float wA, float wB,
                                        float& cb, float& nw)
{
    cb = (h >= ended && h < started) ? 1.f : 0.f;
    nw = (h == ha) ? wA : ((h == ha - 1) ? wB : 0.f);
}

__global__ void k_nw(const float* __restrict__ W_enc,
                     float* __restrict__ out)
{
    const int n   = blockIdx.x;
    const int tid = threadIdx.x;
    const int bd  = blockDim.x;

    const int started = (n < Nn - Ll) ? (n / Ss + 1) : Hh;
    const int ended   = (n >= Ll) ? ((n - Ss) / Ss) : 0;
    const int ha = n / Ss, l0 = n % Ss;
    const float inv_rs = 1.f / g_rowsum[n];
    const float wA = (ha < Hh) ? W_enc[(l0 * Hh + ha) * 3] * inv_rs : 0.f;
    const float wB = (ha >= 1) ? W_enc[((l0 + Ss) * Hh + ha - 1) * 3] * inv_rs : 0.f;

    const int bn = O_NW + n * Hh;
    const int bc = O_CB + n * Hh;
    const int head = (4 - (bn & 3)) & 3;           // bn,bc ≡ n (mod 4)

    for (int h = tid; h < head; h += bd) {
        float cb, nw; nw_vals(h, ended, started, ha, wA, wB, cb, nw);
        out[bn + h] = nw; out[bc + h] = cb;
    }
    const int nvec = (Hh - head) >> 2;
    float4* vn = (float4*)(out + bn + head);
    float4* vc = (float4*)(out + bc + head);
    for (int v = tid; v < nvec; v += bd) {
        int h = head + 4 * v;
        float4 c4, w4;
        nw_vals(h + 0, ended, started, ha, wA, wB, c4.x, w4.x);
        nw_vals(h + 1, ended, started, ha, wA, wB, c4.y, w4.y);
        nw_vals(h + 2, ended, started, ha, wA, wB, c4.z, w4.z);
        nw_vals(h + 3, ended, started, ha, wA, wB, c4.w, w4.w);
        vn[v] = w4; vc[v] = c4;
    }
    for (int h = head + 4 * nvec + tid; h < Hh; h += bd) {
        float cb, nw; nw_vals(h, ended, started, ha, wA, wB, cb, nw);
        out[bn + h] = nw; out[bc + h] = cb;
    }
}

// ---------------------------------------------------------------------------
extern "C" void kernel_launch(void* const* d_in, const int* in_sizes, int n_in,
                              void* d_out, int out_size)
{
    const float* x       = (const float*)d_in[0];
    const float* W_enc   = (const float*)d_in[1];
    const float* W_dec   = (const float*)d_in[2];
    const float* angles  = (const float*)d_in[3];
    const float* scaling = (const float*)d_in[4];
    float* out = (float*)d_out;

    k_tables<<<(HL + 255) / 256, 256>>>(angles, W_enc, W_dec, scaling);

    dim3 gA(HBN, Bb);
    k_encode<<<gA, HBLK>>>(x, W_enc, out);

    k_nw<<<Nn, 256>>>(W_enc, out);
}